// round 12
// baseline (speedup 1.0000x reference)
#include <cuda_runtime.h>
#include <cuda_bf16.h>
#include <math.h>
#include <stdint.h>

#define NB   2
#define TT   2048
#define DD   1024
#define HH   16
#define HDD  64
#define WL   127
#define WR   128

#define SRB  144   // attn smem row stride (bytes)
#define APLB 9216  // attn plane bytes: 64 rows * SRB

// GEMM staging (BM=256, BN=128, BK=32): 64B data + 16B pad per row
#define GSRB 80
#define GA_PL (256 * GSRB)            // 20480 bytes per A plane
#define GB_PL (128 * GSRB)            // 10240 bytes per B plane
#define GSTG  (2 * GA_PL + 2 * GB_PL) // 61440 bytes per stage
#define GSMEM (3 * GSTG)              // 184320 bytes (3-stage ring)

// Scratch (allocation-free)
__device__ float    g_qkv[(size_t)NB * TT * 3 * DD];
__device__ uint16_t g_ahi[(size_t)NB * TT * DD];
__device__ uint16_t g_alo[(size_t)NB * TT * DD];
__device__ uint16_t g_bhi[(size_t)3 * DD * DD];
__device__ uint16_t g_blo[(size_t)3 * DD * DD];
#define APL ((size_t)NB * HH * TT * HDD)
__device__ uint16_t g_qh[APL], g_ql[APL];
__device__ uint16_t g_kh[APL], g_kl[APL];
__device__ uint16_t g_vth[APL], g_vtl[APL];

// ---------------------------------------------------------------------------
__device__ __forceinline__ uint32_t smem_u32(const void* p) {
    uint32_t r;
    asm("{ .reg .u64 t; cvta.to.shared.u64 t, %1; cvt.u32.u64 %0, t; }"
        : "=r"(r) : "l"(p));
    return r;
}
__device__ __forceinline__ void cp_async16(uint32_t s, const void* g) {
    asm volatile("cp.async.cg.shared.global [%0], [%1], 16;" :: "r"(s), "l"(g));
}
__device__ __forceinline__ void cp_commit() {
    asm volatile("cp.async.commit_group;" ::: "memory");
}
template <int N_> __device__ __forceinline__ void cp_wait() {
    asm volatile("cp.async.wait_group %0;" :: "n"(N_) : "memory");
}
__device__ __forceinline__ void ldsm_x4(uint32_t* r, uint32_t addr) {
    asm volatile("ldmatrix.sync.aligned.m8n8.x4.shared.b16 {%0,%1,%2,%3}, [%4];"
                 : "=r"(r[0]), "=r"(r[1]), "=r"(r[2]), "=r"(r[3]) : "r"(addr));
}
__device__ __forceinline__ uint16_t f2bf(float x) {
    return __bfloat16_as_ushort(__float2bfloat16_rn(x));
}
__device__ __forceinline__ uint32_t pack_hi_lo(float a, float b, uint32_t& lo) {
    uint16_t ha = f2bf(a), hb = f2bf(b);
    float ra = a - __uint_as_float((uint32_t)ha << 16);
    float rb = b - __uint_as_float((uint32_t)hb << 16);
    lo = (uint32_t)f2bf(ra) | ((uint32_t)f2bf(rb) << 16);
    return (uint32_t)ha | ((uint32_t)hb << 16);
}

#define MMA_BF16(ACC, A, B0, B1)                                               \
    asm volatile(                                                              \
        "mma.sync.aligned.m16n8k16.row.col.f32.bf16.bf16.f32 "                 \
        "{%0,%1,%2,%3}, {%4,%5,%6,%7}, {%8,%9}, {%0,%1,%2,%3};"                \
        : "+f"(ACC[0]), "+f"(ACC[1]), "+f"(ACC[2]), "+f"(ACC[3])               \
        : "r"((A)[0]), "r"((A)[1]), "r"((A)[2]), "r"((A)[3]), "r"(B0), "r"(B1))

// ---------------------------------------------------------------------------
__global__ __launch_bounds__(256) void split_kernel(
    const float* __restrict__ in, uint16_t* __restrict__ hi,
    uint16_t* __restrict__ lo, int n4)
{
    int i = blockIdx.x * blockDim.x + threadIdx.x;
    if (i >= n4) return;
    float4 v = ((const float4*)in)[i];
    ushort4 h, l;
    h.x = f2bf(v.x); l.x = f2bf(v.x - __uint_as_float((uint32_t)h.x << 16));
    h.y = f2bf(v.y); l.y = f2bf(v.y - __uint_as_float((uint32_t)h.y << 16));
    h.z = f2bf(v.z); l.z = f2bf(v.z - __uint_as_float((uint32_t)h.z << 16));
    h.w = f2bf(v.w); l.w = f2bf(v.w - __uint_as_float((uint32_t)h.w << 16));
    ((ushort4*)hi)[i] = h;
    ((ushort4*)lo)[i] = l;
}

// ---------------------------------------------------------------------------
// 3-term bf16 mma GEMM, BM=256 x BN=128 x BK=32, 512 threads, 3-stage ring.
//   C[m,n] = sum_k A[m,k]*B[n,k] (+ bias[n])
// Requires M%256==0, N%128==0, K%32==0.
// ---------------------------------------------------------------------------
__global__ __launch_bounds__(512) void gemm_3xbf16(
    const uint16_t* __restrict__ Ahi, const uint16_t* __restrict__ Alo,
    const uint16_t* __restrict__ Bhi, const uint16_t* __restrict__ Blo,
    const float* __restrict__ bias, float* __restrict__ C,
    int M, int N, int K)
{
    extern __shared__ char smem[];            // 3 stages x GSTG
    const int tid  = threadIdx.x;
    const int wid  = tid >> 5;                // 0..15
    const int lane = tid & 31;
    const int g    = lane >> 2;
    const int t    = lane & 3;
    const int warpM = (wid >> 2) * 64;        // 0,64,128,192
    const int warpN = (wid & 3) * 32;         // 0,32,64,96
    const int m0 = blockIdx.y * 256;
    const int n0 = blockIdx.x * 128;

    const uint32_t sbase = smem_u32(smem);

    const int aRow = ((lane >> 3) & 1) * 8 + (lane & 7);
    const int aKb  = (lane >> 4) * 16;
    const int bRow = ((lane >> 4) & 1) * 8 + (lane & 7);
    const int bKb  = ((lane >> 3) & 1) * 16;

    // fragment addresses relative to stage base
    uint32_t aOffH[4], aOffL[4], bOffH[2], bOffL[2];
    #pragma unroll
    for (int mi = 0; mi < 4; mi++) {
        uint32_t off = (uint32_t)((warpM + mi * 16 + aRow) * GSRB + aKb);
        aOffH[mi] = sbase + off;
        aOffL[mi] = sbase + GA_PL + off;
    }
    #pragma unroll
    for (int j = 0; j < 2; j++) {
        uint32_t off = (uint32_t)((warpN + j * 16 + bRow) * GSRB + bKb);
        bOffH[j] = sbase + 2u * GA_PL + off;
        bOffL[j] = sbase + 2u * GA_PL + GB_PL + off;
    }

    // stage one BK=32 tile (A 256 rows, B 128 rows; hi+lo planes)
    auto load_tile = [&](int kt, int st) {
        const uint32_t dst = sbase + (uint32_t)st * GSTG;
        // A planes: 2 planes x 256 rows x 4 chunks = 2048 chunks
        #pragma unroll
        for (int c = 0; c < 4; c++) {
            int idx = tid + c * 512;          // 0..2047
            int pl  = idx >> 10;              // 0=hi, 1=lo
            int r   = (idx >> 2) & 255;
            int j   = idx & 3;
            const uint16_t* gp = pl ? Alo : Ahi;
            cp_async16(dst + pl * (uint32_t)GA_PL + (uint32_t)(r * GSRB + j * 16),
                       gp + (size_t)(m0 + r) * K + kt * 32 + j * 8);
        }
        // B planes: 2 planes x 128 rows x 4 chunks = 1024 chunks
        #pragma unroll
        for (int c = 0; c < 2; c++) {
            int idx = tid + c * 512;          // 0..1023
            int pl  = idx >> 9;
            int r   = (idx >> 2) & 127;
            int j   = idx & 3;
            const uint16_t* gp = pl ? Blo : Bhi;
            cp_async16(dst + 2u * GA_PL + pl * (uint32_t)GB_PL
                           + (uint32_t)(r * GSRB + j * 16),
                       gp + (size_t)(n0 + r) * K + kt * 32 + j * 8);
        }
        cp_commit();
    };

    float acc[4][4][4];
    #pragma unroll
    for (int mi = 0; mi < 4; mi++)
        #pragma unroll
        for (int ni = 0; ni < 4; ni++)
            #pragma unroll
            for (int r = 0; r < 4; r++) acc[mi][ni][r] = 0.0f;

    const int ktiles = K / 32;                // 32
    load_tile(0, 0);
    load_tile(1, 1);

    int st = 0;                               // stage of tile kt
    for (int kt = 0; kt < ktiles; kt++) {
        if (kt == ktiles - 1) cp_wait<0>(); else cp_wait<1>();
        __syncthreads();
        if (kt + 2 < ktiles) {
            int st2 = st + 2; if (st2 >= 3) st2 -= 3;
            load_tile(kt + 2, st2);
        }

        const uint32_t bo = (uint32_t)st * GSTG;
        #pragma unroll
        for (int s = 0; s < 2; s++) {         // 2 k16-steps in BK=32
            const uint32_t so = bo + (uint32_t)s * 32u;
            uint32_t ah[4][4], al[4][4], bfh[2][4], bfl[2][4];
            #pragma unroll
            for (int mi = 0; mi < 4; mi++) ldsm_x4(ah[mi], aOffH[mi] + so);
            #pragma unroll
            for (int mi = 0; mi < 4; mi++) ldsm_x4(al[mi], aOffL[mi] + so);
            #pragma unroll
            for (int j = 0; j < 2; j++) ldsm_x4(bfh[j], bOffH[j] + so);
            #pragma unroll
            for (int j = 0; j < 2; j++) ldsm_x4(bfl[j], bOffL[j] + so);

            #pragma unroll
            for (int mi = 0; mi < 4; mi++)
                #pragma unroll
                for (int ni = 0; ni < 4; ni++) {
                    const uint32_t* Bh = &bfh[ni >> 1][(ni & 1) * 2];
                    const uint32_t* Bl = &bfl[ni >> 1][(ni & 1) * 2];
                    MMA_BF16(acc[mi][ni], al[mi], Bh[0], Bh[1]);
                    MMA_BF16(acc[mi][ni], ah[mi], Bl[0], Bl[1]);
                    MMA_BF16(acc[mi][ni], ah[mi], Bh[0], Bh[1]);
                }
        }
        if (++st == 3) st = 0;
    }

    #pragma unroll
    for (int mi = 0; mi < 4; mi++) {
        const int row = m0 + warpM + mi * 16 + g;
        #pragma unroll
        for (int ni = 0; ni < 4; ni++) {
            const int col = n0 + warpN + ni * 8 + t * 2;
            float bx = 0.f, by = 0.f;
            if (bias) { bx = bias[col]; by = bias[col + 1]; }
            float2 v0 = make_float2(acc[mi][ni][0] + bx, acc[mi][ni][1] + by);
            float2 v1 = make_float2(acc[mi][ni][2] + bx, acc[mi][ni][3] + by);
            *(float2*)(C + (size_t)row * N + col)       = v0;
            *(float2*)(C + (size_t)(row + 8) * N + col) = v1;
        }
    }
}

// ---------------------------------------------------------------------------
// RoPE + bf16 hi/lo split of q (scaled by 1/8) and k into [n,h,t,64] planes.
// ---------------------------------------------------------------------------
__global__ __launch_bounds__(256) void rope_split(
    const float* __restrict__ qkv,
    uint16_t* __restrict__ qh, uint16_t* __restrict__ ql,
    uint16_t* __restrict__ kh, uint16_t* __restrict__ kl)
{
    int idx = blockIdx.x * blockDim.x + threadIdx.x;
    int d  = idx & 31;
    int h  = (idx >> 5) & 15;
    int p  = (idx >> 9) & 1;
    int nt = idx >> 10;
    int t  = nt & (TT - 1);
    int n  = nt >> 11;

    float inv = exp2f(-0.41524101186092029f * (float)d);
    float fr  = (float)t * inv;
    float c, s;
    sincosf(fr, &s, &c);

    size_t base = ((size_t)nt * 3 + p) * DD + h * HDD + d;
    float x1 = qkv[base];
    float x2 = qkv[base + 32];
    float y1 = x1 * c - x2 * s;
    float y2 = x2 * c + x1 * s;
    if (p == 0) { y1 *= 0.125f; y2 *= 0.125f; }

    uint16_t* H = p ? kh : qh;
    uint16_t* L = p ? kl : ql;
    size_t dst = ((size_t)((n * HH + h) * TT) + t) * HDD + d;
    uint16_t h1 = f2bf(y1);
    uint16_t h2 = f2bf(y2);
    H[dst]      = h1;
    H[dst + 32] = h2;
    L[dst]      = f2bf(y1 - __uint_as_float((uint32_t)h1 << 16));
    L[dst + 32] = f2bf(y2 - __uint_as_float((uint32_t)h2 << 16));
}

// ---------------------------------------------------------------------------
// V transpose + split: qkv v part -> planes [n,h,d,t] hi/lo.
// ---------------------------------------------------------------------------
__global__ __launch_bounds__(256) void vtrans_split(
    const float* __restrict__ qkv,
    uint16_t* __restrict__ vh, uint16_t* __restrict__ vl)
{
    __shared__ float vs[64 * 65];
    const int t0 = blockIdx.x * 64;
    const int h  = blockIdx.y;
    const int n  = blockIdx.z;
    const int tid = threadIdx.x;

    for (int e = tid; e < 4096; e += 256) {
        int tr = e >> 6, d = e & 63;
        float v = qkv[(((size_t)(n * TT + t0 + tr) * 3) + 2) * DD + h * HDD + d];
        vs[d * 65 + tr] = v;
    }
    __syncthreads();
    for (int e = tid; e < 4096; e += 256) {
        int d = e >> 6, tc = e & 63;
        float v = vs[d * 65 + tc];
        uint16_t hb = f2bf(v);
        size_t dst = ((size_t)((n * HH + h) * HDD) + d) * TT + t0 + tc;
        vh[dst] = hb;
        vl[dst] = f2bf(v - __uint_as_float((uint32_t)hb << 16));
    }
}

// ---------------------------------------------------------------------------
// Flash attention, 3-term bf16 mma (unchanged from R10/R11 passing version).
// ---------------------------------------------------------------------------
__global__ __launch_bounds__(128) void attn_mma(
    const uint16_t* __restrict__ Qh, const uint16_t* __restrict__ Ql,
    const uint16_t* __restrict__ Kh, const uint16_t* __restrict__ Kl,
    const uint16_t* __restrict__ Vh, const uint16_t* __restrict__ Vl,
    uint16_t* __restrict__ Oh, uint16_t* __restrict__ Ol)
{
    __shared__ char smem[4 * APLB];
    const uint32_t sb = smem_u32(smem);
    const uint32_t sKh = sb, sKl = sb + APLB, sVh = sb + 2 * APLB, sVl = sb + 3 * APLB;

    const int q0 = blockIdx.x * 64;
    const int h  = blockIdx.y;
    const int n  = blockIdx.z;
    const int tid = threadIdx.x;
    const int wid = tid >> 5;
    const int lane = tid & 31;
    const int g = lane >> 2;
    const int t = lane & 3;

    const size_t headoff  = (size_t)(n * HH + h) * TT * HDD;
    const size_t vheadoff = (size_t)(n * HH + h) * HDD * TT;

    const int aRow = ((lane >> 3) & 1) * 8 + (lane & 7);
    const int aKb  = (lane >> 4) * 16;
    const int bRow = ((lane >> 4) & 1) * 8 + (lane & 7);
    const int bKb  = ((lane >> 3) & 1) * 16;

    {
        #pragma unroll
        for (int c = 0; c < 4; c++) {
            int idx = tid + c * 128;
            int row = idx >> 3, j = idx & 7;
            uint32_t soff = (uint32_t)(row * SRB + j * 16);
            cp_async16(sKh + soff, Qh + headoff + (size_t)(q0 + row) * HDD + j * 8);
            cp_async16(sKl + soff, Ql + headoff + (size_t)(q0 + row) * HDD + j * 8);
        }
        cp_commit(); cp_wait<0>();
        __syncthreads();
    }
    uint32_t qfh[4][4], qfl[4][4];
    #pragma unroll
    for (int s = 0; s < 4; s++) {
        uint32_t off = (uint32_t)((wid * 16 + aRow) * SRB + aKb + s * 32);
        ldsm_x4(qfh[s], sKh + off);
        ldsm_x4(qfl[s], sKl + off);
    }
    __syncthreads();

    float O[8][4];
    #pragma unroll
    for (int nd = 0; nd < 8; nd++)
        #pragma unroll
        for (int c = 0; c < 4; c++) O[nd][c] = 0.0f;
    float m0 = -1e30f, m1 = -1e30f, l0 = 0.0f, l1 = 0.0f;

    const int klo = max(0, q0 - WL);
    const int khi = min(TT - 1, q0 + 63 + WR);
    const int i0  = q0 + wid * 16 + g;

    for (int kt = klo & ~63; kt <= khi; kt += 64) {
        #pragma unroll
        for (int c = 0; c < 4; c++) {
            int idx = tid + c * 128;
            int row = idx >> 3, j = idx & 7;
            uint32_t soff = (uint32_t)(row * SRB + j * 16);
            cp_async16(sKh + soff, Kh + headoff + (size_t)(kt + row) * HDD + j * 8);
            cp_async16(sKl + soff, Kl + headoff + (size_t)(kt + row) * HDD + j * 8);
            cp_async16(sVh + soff, Vh + vheadoff + (size_t)row * TT + kt + j * 8);
            cp_async16(sVl + soff, Vl + vheadoff + (size_t)row * TT + kt + j * 8);
        }
        cp_commit(); cp_wait<0>();
        __syncthreads();

        float S[8][4];
        #pragma unroll
        for (int nt = 0; nt < 8; nt++)
            #pragma unroll
            for (int c = 0; c < 4; c++) S[nt][c] = 0.0f;

        #pragma unroll
        for (int s = 0; s < 4; s++) {
            uint32_t kbh[4][4], kbl[4][4];
            #pragma unroll
            for (int j = 0; j < 4; j++) {
                uint32_t off = (uint32_t)((j * 16 + bRow) * SRB + bKb + s * 32);
                ldsm_x4(kbh[j], sKh + off);
                ldsm_x4(kbl[j], sKl + off);
            }
            #pragma unroll
            for (int nt = 0; nt < 8; nt++) {
                const uint32_t* Bh = &kbh[nt >> 1][(nt & 1) * 2];
                const uint32_t* Bl = &kbl[nt >> 1][(nt & 1) * 2];
                MMA_BF16(S[nt], qfl[s], Bh[0], Bh[1]);
                MMA_BF16(S[nt], qfh[s], Bl[0], Bl[1]);
                MMA_BF16(S[nt], qfh[s], Bh[0], Bh[1]);
            }
        }

        if (kt < q0 - 64 || kt > q0 + 64) {
            #pragma unroll
            for (int nt = 0; nt < 8; nt++)
                #pragma unroll
                for (int c = 0; c < 4; c++) {
                    int j = kt + nt * 8 + 2 * t + (c & 1);
                    int i = i0 + ((c >> 1) << 3);
                    if (j < i - WL || j > i + WR) S[nt][c] = -1e30f;
                }
        }

        float mx0 = -1e30f, mx1 = -1e30f;
        #pragma unroll
        for (int nt = 0; nt < 8; nt++) {
            mx0 = fmaxf(mx0, fmaxf(S[nt][0], S[nt][1]));
            mx1 = fmaxf(mx1, fmaxf(S[nt][2], S[nt][3]));
        }
        mx0 = fmaxf(mx0, __shfl_xor_sync(0xffffffffu, mx0, 1));
        mx0 = fmaxf(mx0, __shfl_xor_sync(0xffffffffu, mx0, 2));
        mx1 = fmaxf(mx1, __shfl_xor_sync(0xffffffffu, mx1, 1));
        mx1 = fmaxf(mx1, __shfl_xor_sync(0xffffffffu, mx1, 2));

        float mn0 = fmaxf(m0, mx0), mn1 = fmaxf(m1, mx1);
        float cr0 = __expf(m0 - mn0), cr1 = __expf(m1 - mn1);
        float mc0 = fmaxf(mn0, -1e29f), mc1 = fmaxf(mn1, -1e29f);

        float sum0 = 0.0f, sum1 = 0.0f;
        #pragma unroll
        for (int nt = 0; nt < 8; nt++) {
            S[nt][0] = __expf(S[nt][0] - mc0);
            S[nt][1] = __expf(S[nt][1] - mc0);
            S[nt][2] = __expf(S[nt][2] - mc1);
            S[nt][3] = __expf(S[nt][3] - mc1);
            sum0 += S[nt][0] + S[nt][1];
            sum1 += S[nt][2] + S[nt][3];
        }
        sum0 += __shfl_xor_sync(0xffffffffu, sum0, 1);
        sum0 += __shfl_xor_sync(0xffffffffu, sum0, 2);
        sum1 += __shfl_xor_sync(0xffffffffu, sum1, 1);
        sum1 += __shfl_xor_sync(0xffffffffu, sum1, 2);
        l0 = l0 * cr0 + sum0;
        l1 = l1 * cr1 + sum1;
        m0 = mn0; m1 = mn1;

        #pragma unroll
        for (int nd = 0; nd < 8; nd++) {
            O[nd][0] *= cr0; O[nd][1] *= cr0;
            O[nd][2] *= cr1; O[nd][3] *= cr1;
        }

        #pragma unroll
        for (int s2 = 0; s2 < 4; s2++) {
            uint32_t pah[4], pal[4];
            pah[0] = pack_hi_lo(S[2 * s2][0],     S[2 * s2][1],     pal[0]);
            pah[1] = pack_hi_lo(S[2 * s2][2],     S[2 * s2][3],     pal[1]);
            pah[2] = pack_hi_lo(S[2 * s2 + 1][0], S[2 * s2 + 1][1], pal[2]);
            pah[3] = pack_hi_lo(S[2 * s2 + 1][2], S[2 * s2 + 1][3], pal[3]);

            uint32_t vbh[4][4], vbl[4][4];
            #pragma unroll
            for (int j = 0; j < 4; j++) {
                uint32_t off = (uint32_t)((j * 16 + bRow) * SRB + bKb + s2 * 32);
                ldsm_x4(vbh[j], sVh + off);
                ldsm_x4(vbl[j], sVl + off);
            }
            #pragma unroll
            for (int nd = 0; nd < 8; nd++) {
                const uint32_t* Bh = &vbh[nd >> 1][(nd & 1) * 2];
                const uint32_t* Bl = &vbl[nd >> 1][(nd & 1) * 2];
                MMA_BF16(O[nd], pal, Bh[0], Bh[1]);
                MMA_BF16(O[nd], pah, Bl[0], Bl[1]);
                MMA_BF16(O[nd], pah, Bh[0], Bh[1]);
            }
        }
        __syncthreads();
    }

    const float inv0 = 1.0f / l0, inv1 = 1.0f / l1;
    const int r0 = i0, r1 = i0 + 8;
    #pragma unroll
    for (int nd = 0; nd < 8; nd++) {
        const int col = h * HDD + nd * 8 + 2 * t;
        uint32_t lo0, lo1;
        uint32_t hi0 = pack_hi_lo(O[nd][0] * inv0, O[nd][1] * inv0, lo0);
        uint32_t hi1 = pack_hi_lo(O[nd][2] * inv1, O[nd][3] * inv1, lo1);
        *(uint32_t*)(Oh + (size_t)(n * TT + r0) * DD + col) = hi0;
        *(uint32_t*)(Ol + (size_t)(n * TT + r0) * DD + col) = lo0;
        *(uint32_t*)(Oh + (size_t)(n * TT + r1) * DD + col) = hi1;
        *(uint32_t*)(Ol + (size_t)(n * TT + r1) * DD + col) = lo1;
    }
}

// ---------------------------------------------------------------------------
extern "C" void kernel_launch(void* const* d_in, const int* in_sizes, int n_in,
                              void* d_out, int out_size)
{
    const float* x     = (const float*)d_in[0];
    const float* w_qkv = (const float*)d_in[1];
    const float* w_out = (const float*)d_in[2];
    const float* b_out = (const float*)d_in[3];
    float* out = (float*)d_out;

    float* qkv = nullptr;
    uint16_t *ahi, *alo, *bhi, *blo, *qh, *ql, *kh, *kl, *vth, *vtl;
    cudaGetSymbolAddress((void**)&qkv, g_qkv);
    cudaGetSymbolAddress((void**)&ahi, g_ahi);
    cudaGetSymbolAddress((void**)&alo, g_alo);
    cudaGetSymbolAddress((void**)&bhi, g_bhi);
    cudaGetSymbolAddress((void**)&blo, g_blo);
    cudaGetSymbolAddress((void**)&qh,  g_qh);
    cudaGetSymbolAddress((void**)&ql,  g_ql);
    cudaGetSymbolAddress((void**)&kh,  g_kh);
    cudaGetSymbolAddress((void**)&kl,  g_kl);
    cudaGetSymbolAddress((void**)&vth, g_vth);
    cudaGetSymbolAddress((void**)&vtl, g_vtl);

    const int M = NB * TT;                 // 4096

    cudaFuncSetAttribute(gemm_3xbf16, cudaFuncAttributeMaxDynamicSharedMemorySize,
                         GSMEM);

    // split x and w_qkv
    {
        int n4 = M * DD / 4;
        split_kernel<<<(n4 + 255) / 256, 256>>>(x, ahi, alo, n4);
        n4 = 3 * DD * DD / 4;
        split_kernel<<<(n4 + 255) / 256, 256>>>(w_qkv, bhi, blo, n4);
    }
    // 1) qkv = x @ w_qkv^T
    {
        dim3 grid(3 * DD / 128, M / 256);
        gemm_3xbf16<<<grid, 512, GSMEM>>>(ahi, alo, bhi, blo, nullptr, qkv,
                                          M, 3 * DD, DD);
    }
    // 2) RoPE + split Q,K ; transpose + split V
    {
        int total = NB * TT * 2 * HH * 32;
        rope_split<<<total / 256, 256>>>(qkv, qh, ql, kh, kl);
        dim3 grid(TT / 64, HH, NB);
        vtrans_split<<<grid, 256>>>(qkv, vth, vtl);
    }
    // 3) flash attention -> writes A planes for GEMM2
    {
        dim3 grid(TT / 64, HH, NB);
        attn_mma<<<grid, 128>>>(qh, ql, kh, kl, vth, vtl, ahi, alo);
    }
    // split w_out
    {
        int n4 = DD * DD / 4;
        split_kernel<<<(n4 + 255) / 256, 256>>>(w_out, bhi, blo, n4);
    }
    // 4) out = attn @ w_out^T + b_out
    {
        dim3 grid(DD / 128, M / 256);
        gemm_3xbf16<<<grid, 512, GSMEM>>>(ahi, alo, bhi, blo, b_out, out,
                                          M, DD, DD);
    }
}

// round 13
// speedup vs baseline: 1.0547x; 1.0547x over previous
#include <cuda_runtime.h>
#include <cuda_bf16.h>
#include <math.h>
#include <stdint.h>

#define NB   2
#define TT   2048
#define DD   1024
#define HH   16
#define HDD  64
#define WL   127
#define WR   128

#define SRB  144   // attn smem row stride (bytes)
#define APLB 9216  // attn plane bytes: 64 rows * SRB

// GEMM staging (BK=32): 64B data + 16B pad per row
#define GSRB 80
#define GPLB (128 * GSRB)    // 10240
#define GBUF (4 * GPLB)      // 40960 bytes per stage (4 planes)
#define GSMEM (2 * GBUF)     // 81920 (also holds 128x132 fp32 epilogue tile: 67584)

// Scratch (allocation-free)
__device__ uint16_t g_ahi[(size_t)NB * TT * DD];
__device__ uint16_t g_alo[(size_t)NB * TT * DD];
__device__ uint16_t g_bhi[(size_t)3 * DD * DD];
__device__ uint16_t g_blo[(size_t)3 * DD * DD];
#define APL ((size_t)NB * HH * TT * HDD)
__device__ uint16_t g_qh[APL], g_ql[APL];
__device__ uint16_t g_kh[APL], g_kl[APL];
__device__ uint16_t g_vth[APL], g_vtl[APL];

// ---------------------------------------------------------------------------
__device__ __forceinline__ uint32_t smem_u32(const void* p) {
    uint32_t r;
    asm("{ .reg .u64 t; cvta.to.shared.u64 t, %1; cvt.u32.u64 %0, t; }"
        : "=r"(r) : "l"(p));
    return r;
}
__device__ __forceinline__ void cp_async16(uint32_t s, const void* g) {
    asm volatile("cp.async.cg.shared.global [%0], [%1], 16;" :: "r"(s), "l"(g));
}
__device__ __forceinline__ void cp_commit() {
    asm volatile("cp.async.commit_group;" ::: "memory");
}
template <int N_> __device__ __forceinline__ void cp_wait() {
    asm volatile("cp.async.wait_group %0;" :: "n"(N_) : "memory");
}
__device__ __forceinline__ void ldsm_x4(uint32_t* r, uint32_t addr) {
    asm volatile("ldmatrix.sync.aligned.m8n8.x4.shared.b16 {%0,%1,%2,%3}, [%4];"
                 : "=r"(r[0]), "=r"(r[1]), "=r"(r[2]), "=r"(r[3]) : "r"(addr));
}
__device__ __forceinline__ uint16_t f2bf(float x) {
    return __bfloat16_as_ushort(__float2bfloat16_rn(x));
}
__device__ __forceinline__ uint32_t pack_hi_lo(float a, float b, uint32_t& lo) {
    uint16_t ha = f2bf(a), hb = f2bf(b);
    float ra = a - __uint_as_float((uint32_t)ha << 16);
    float rb = b - __uint_as_float((uint32_t)hb << 16);
    lo = (uint32_t)f2bf(ra) | ((uint32_t)f2bf(rb) << 16);
    return (uint32_t)ha | ((uint32_t)hb << 16);
}

#define MMA_BF16(ACC, A, B0, B1)                                               \
    asm volatile(                                                              \
        "mma.sync.aligned.m16n8k16.row.col.f32.bf16.bf16.f32 "                 \
        "{%0,%1,%2,%3}, {%4,%5,%6,%7}, {%8,%9}, {%0,%1,%2,%3};"                \
        : "+f"(ACC[0]), "+f"(ACC[1]), "+f"(ACC[2]), "+f"(ACC[3])               \
        : "r"((A)[0]), "r"((A)[1]), "r"((A)[2]), "r"((A)[3]), "r"(B0), "r"(B1))

// ---------------------------------------------------------------------------
__global__ __launch_bounds__(256) void split_kernel(
    const float* __restrict__ in, uint16_t* __restrict__ hi,
    uint16_t* __restrict__ lo, int n4)
{
    int i = blockIdx.x * blockDim.x + threadIdx.x;
    if (i >= n4) return;
    float4 v = ((const float4*)in)[i];
    ushort4 h, l;
    h.x = f2bf(v.x); l.x = f2bf(v.x - __uint_as_float((uint32_t)h.x << 16));
    h.y = f2bf(v.y); l.y = f2bf(v.y - __uint_as_float((uint32_t)h.y << 16));
    h.z = f2bf(v.z); l.z = f2bf(v.z - __uint_as_float((uint32_t)h.z << 16));
    h.w = f2bf(v.w); l.w = f2bf(v.w - __uint_as_float((uint32_t)h.w << 16));
    ((ushort4*)hi)[i] = h;
    ((ushort4*)lo)[i] = l;
}

// ---------------------------------------------------------------------------
// 3-term bf16 mma GEMM, 128x128xBK32 (R11 config).
// mode 0: C = A@B^T + bias (fp32 out).
// mode 1: fused qkv epilogue — RoPE+split q,k into g_q*/g_k* planes,
//         transpose+split v into g_vt* planes. C unused.
// ---------------------------------------------------------------------------
__global__ __launch_bounds__(256) void gemm_3xbf16(
    const uint16_t* __restrict__ Ahi, const uint16_t* __restrict__ Alo,
    const uint16_t* __restrict__ Bhi, const uint16_t* __restrict__ Blo,
    const float* __restrict__ bias, float* __restrict__ C,
    int M, int N, int K, int mode)
{
    extern __shared__ char smem[];            // 2 stages x GBUF
    const int tid  = threadIdx.x;
    const int wid  = tid >> 5;
    const int lane = tid & 31;
    const int g    = lane >> 2;
    const int t    = lane & 3;
    const int warpM = (wid >> 2) * 64;
    const int warpN = (wid & 3) * 32;
    const int m0 = blockIdx.y * 128;
    const int n0 = blockIdx.x * 128;

    const uint32_t sbase = smem_u32(smem);

    const int aRow = ((lane >> 3) & 1) * 8 + (lane & 7);
    const int aKb  = (lane >> 4) * 16;
    const int bRow = ((lane >> 4) & 1) * 8 + (lane & 7);
    const int bKb  = ((lane >> 3) & 1) * 16;

    uint32_t aOffH[4], aOffL[4], bOffH[2], bOffL[2];
    #pragma unroll
    for (int mi = 0; mi < 4; mi++) {
        uint32_t off = (uint32_t)((warpM + mi * 16 + aRow) * GSRB + aKb);
        aOffH[mi] = sbase + off;
        aOffL[mi] = sbase + GPLB + off;
    }
    #pragma unroll
    for (int j = 0; j < 2; j++) {
        uint32_t off = (uint32_t)((warpN + j * 16 + bRow) * GSRB + bKb);
        bOffH[j] = sbase + 2u * GPLB + off;
        bOffL[j] = sbase + 3u * GPLB + off;
    }

    auto load_tile = [&](int kt, int b) {
        const uint32_t dst = sbase + (uint32_t)b * GBUF;
        const uint16_t* gp[4];
        gp[0] = Ahi + (size_t)m0 * K + kt * 32;
        gp[1] = Alo + (size_t)m0 * K + kt * 32;
        gp[2] = Bhi + (size_t)n0 * K + kt * 32;
        gp[3] = Blo + (size_t)n0 * K + kt * 32;
        #pragma unroll
        for (int c = 0; c < 2; c++) {
            int idx = tid + c * 256;          // 0..511
            int row = idx >> 2, j = idx & 3;
            uint32_t soff = (uint32_t)(row * GSRB + j * 16);
            #pragma unroll
            for (int pl = 0; pl < 4; pl++)
                cp_async16(dst + pl * (uint32_t)GPLB + soff,
                           gp[pl] + (size_t)row * K + j * 8);
        }
        cp_commit();
    };

    float acc[4][4][4];
    #pragma unroll
    for (int mi = 0; mi < 4; mi++)
        #pragma unroll
        for (int ni = 0; ni < 4; ni++)
            #pragma unroll
            for (int r = 0; r < 4; r++) acc[mi][ni][r] = 0.0f;

    const int ktiles = K / 32;
    load_tile(0, 0);

    for (int kt = 0; kt < ktiles; kt++) {
        const int buf = kt & 1;
        if (kt + 1 < ktiles) { load_tile(kt + 1, buf ^ 1); cp_wait<1>(); }
        else                 { cp_wait<0>(); }
        __syncthreads();

        const uint32_t bo = (uint32_t)buf * GBUF;

        #pragma unroll
        for (int s = 0; s < 2; s++) {
            const uint32_t so = bo + (uint32_t)s * 32u;
            uint32_t ah[4][4], al[4][4], bfh[2][4], bfl[2][4];
            #pragma unroll
            for (int mi = 0; mi < 4; mi++) ldsm_x4(ah[mi], aOffH[mi] + so);
            #pragma unroll
            for (int mi = 0; mi < 4; mi++) ldsm_x4(al[mi], aOffL[mi] + so);
            #pragma unroll
            for (int j = 0; j < 2; j++) ldsm_x4(bfh[j], bOffH[j] + so);
            #pragma unroll
            for (int j = 0; j < 2; j++) ldsm_x4(bfl[j], bOffL[j] + so);

            #pragma unroll
            for (int mi = 0; mi < 4; mi++)
                #pragma unroll
                for (int ni = 0; ni < 4; ni++) {
                    const uint32_t* Bh = &bfh[ni >> 1][(ni & 1) * 2];
                    const uint32_t* Bl = &bfl[ni >> 1][(ni & 1) * 2];
                    MMA_BF16(acc[mi][ni], al[mi], Bh[0], Bh[1]);
                    MMA_BF16(acc[mi][ni], ah[mi], Bl[0], Bl[1]);
                    MMA_BF16(acc[mi][ni], ah[mi], Bh[0], Bh[1]);
                }
        }
        __syncthreads();
    }

    if (mode == 0) {
        #pragma unroll
        for (int mi = 0; mi < 4; mi++) {
            const int row = m0 + warpM + mi * 16 + g;
            #pragma unroll
            for (int ni = 0; ni < 4; ni++) {
                const int col = n0 + warpN + ni * 8 + t * 2;
                float bx = bias ? bias[col] : 0.f;
                float by = bias ? bias[col + 1] : 0.f;
                float2 v0 = make_float2(acc[mi][ni][0] + bx, acc[mi][ni][1] + by);
                float2 v1 = make_float2(acc[mi][ni][2] + bx, acc[mi][ni][3] + by);
                *(float2*)(C + (size_t)row * N + col)       = v0;
                *(float2*)(C + (size_t)(row + 8) * N + col) = v1;
            }
        }
        return;
    }

    // ---- mode 1: fused qkv epilogue ----
    // stage fp32 tile into smem (reuses staging memory; mainloop done)
    float* Cs = (float*)smem;                 // [128][132]
    #pragma unroll
    for (int mi = 0; mi < 4; mi++) {
        const int r = warpM + mi * 16 + g;
        #pragma unroll
        for (int ni = 0; ni < 4; ni++) {
            const int c = warpN + ni * 8 + t * 2;
            Cs[r * 132 + c]           = acc[mi][ni][0];
            Cs[r * 132 + c + 1]       = acc[mi][ni][1];
            Cs[(r + 8) * 132 + c]     = acc[mi][ni][2];
            Cs[(r + 8) * 132 + c + 1] = acc[mi][ni][3];
        }
    }
    __syncthreads();

    const int region = n0 >> 10;              // 0=q, 1=k, 2=v
    const int h0 = (n0 & 1023) >> 6;          // first of 2 heads in this tile

    if (region < 2) {
        uint16_t* H = region ? g_kh : g_qh;
        uint16_t* L = region ? g_kl : g_ql;
        const float scale = region ? 1.0f : 0.125f;
        for (int e = tid; e < 8192; e += 256) {
            int r  = e >> 6;
            int p  = e & 63;
            int hh = p >> 5;
            int d  = p & 31;
            int m  = m0 + r;
            int tp = m & (TT - 1);
            int nb = m >> 11;
            float x1 = Cs[r * 132 + hh * 64 + d];
            float x2 = Cs[r * 132 + hh * 64 + d + 32];
            float inv = exp2f(-0.41524101186092029f * (float)d);
            float fr  = (float)tp * inv;
            float c, s;
            sincosf(fr, &s, &c);
            float y1 = (x1 * c - x2 * s) * scale;
            float y2 = (x2 * c + x1 * s) * scale;
            size_t dst = ((size_t)((nb * HH + h0 + hh) * TT) + tp) * HDD + d;
            uint16_t h1 = f2bf(y1);
            uint16_t h2 = f2bf(y2);
            H[dst]      = h1;
            H[dst + 32] = h2;
            L[dst]      = f2bf(y1 - __uint_as_float((uint32_t)h1 << 16));
            L[dst + 32] = f2bf(y2 - __uint_as_float((uint32_t)h2 << 16));
        }
    } else {
        for (int e = tid; e < 16384; e += 256) {
            int cidx = e >> 7;
            int r    = e & 127;
            int m  = m0 + r;
            int tp = m & (TT - 1);
            int nb = m >> 11;
            int hh = cidx >> 6;
            int d  = cidx & 63;
            float v = Cs[r * 132 + cidx];
            uint16_t hb = f2bf(v);
            size_t dst = ((size_t)((nb * HH + h0 + hh) * HDD) + d) * TT + tp;
            g_vth[dst] = hb;
            g_vtl[dst] = f2bf(v - __uint_as_float((uint32_t)hb << 16));
        }
    }
}

// ---------------------------------------------------------------------------
// Flash attention, 3-term bf16 mma (unchanged from R11 passing version).
// ---------------------------------------------------------------------------
__global__ __launch_bounds__(128) void attn_mma(
    const uint16_t* __restrict__ Qh, const uint16_t* __restrict__ Ql,
    const uint16_t* __restrict__ Kh, const uint16_t* __restrict__ Kl,
    const uint16_t* __restrict__ Vh, const uint16_t* __restrict__ Vl,
    uint16_t* __restrict__ Oh, uint16_t* __restrict__ Ol)
{
    __shared__ char smem[4 * APLB];
    const uint32_t sb = smem_u32(smem);
    const uint32_t sKh = sb, sKl = sb + APLB, sVh = sb + 2 * APLB, sVl = sb + 3 * APLB;

    const int q0 = blockIdx.x * 64;
    const int h  = blockIdx.y;
    const int n  = blockIdx.z;
    const int tid = threadIdx.x;
    const int wid = tid >> 5;
    const int lane = tid & 31;
    const int g = lane >> 2;
    const int t = lane & 3;

    const size_t headoff  = (size_t)(n * HH + h) * TT * HDD;
    const size_t vheadoff = (size_t)(n * HH + h) * HDD * TT;

    const int aRow = ((lane >> 3) & 1) * 8 + (lane & 7);
    const int aKb  = (lane >> 4) * 16;
    const int bRow = ((lane >> 4) & 1) * 8 + (lane & 7);
    const int bKb  = ((lane >> 3) & 1) * 16;

    {
        #pragma unroll
        for (int c = 0; c < 4; c++) {
            int idx = tid + c * 128;
            int row = idx >> 3, j = idx & 7;
            uint32_t soff = (uint32_t)(row * SRB + j * 16);
            cp_async16(sKh + soff, Qh + headoff + (size_t)(q0 + row) * HDD + j * 8);
            cp_async16(sKl + soff, Ql + headoff + (size_t)(q0 + row) * HDD + j * 8);
        }
        cp_commit(); cp_wait<0>();
        __syncthreads();
    }
    uint32_t qfh[4][4], qfl[4][4];
    #pragma unroll
    for (int s = 0; s < 4; s++) {
        uint32_t off = (uint32_t)((wid * 16 + aRow) * SRB + aKb + s * 32);
        ldsm_x4(qfh[s], sKh + off);
        ldsm_x4(qfl[s], sKl + off);
    }
    __syncthreads();

    float O[8][4];
    #pragma unroll
    for (int nd = 0; nd < 8; nd++)
        #pragma unroll
        for (int c = 0; c < 4; c++) O[nd][c] = 0.0f;
    float m0 = -1e30f, m1 = -1e30f, l0 = 0.0f, l1 = 0.0f;

    const int klo = max(0, q0 - WL);
    const int khi = min(TT - 1, q0 + 63 + WR);
    const int i0  = q0 + wid * 16 + g;

    for (int kt = klo & ~63; kt <= khi; kt += 64) {
        #pragma unroll
        for (int c = 0; c < 4; c++) {
            int idx = tid + c * 128;
            int row = idx >> 3, j = idx & 7;
            uint32_t soff = (uint32_t)(row * SRB + j * 16);
            cp_async16(sKh + soff, Kh + headoff + (size_t)(kt + row) * HDD + j * 8);
            cp_async16(sKl + soff, Kl + headoff + (size_t)(kt + row) * HDD + j * 8);
            cp_async16(sVh + soff, Vh + vheadoff + (size_t)row * TT + kt + j * 8);
            cp_async16(sVl + soff, Vl + vheadoff + (size_t)row * TT + kt + j * 8);
        }
        cp_commit(); cp_wait<0>();
        __syncthreads();

        float S[8][4];
        #pragma unroll
        for (int nt = 0; nt < 8; nt++)
            #pragma unroll
            for (int c = 0; c < 4; c++) S[nt][c] = 0.0f;

        #pragma unroll
        for (int s = 0; s < 4; s++) {
            uint32_t kbh[4][4], kbl[4][4];
            #pragma unroll
            for (int j = 0; j < 4; j++) {
                uint32_t off = (uint32_t)((j * 16 + bRow) * SRB + bKb + s * 32);
                ldsm_x4(kbh[j], sKh + off);
                ldsm_x4(kbl[j], sKl + off);
            }
            #pragma unroll
            for (int nt = 0; nt < 8; nt++) {
                const uint32_t* Bh = &kbh[nt >> 1][(nt & 1) * 2];
                const uint32_t* Bl = &kbl[nt >> 1][(nt & 1) * 2];
                MMA_BF16(S[nt], qfl[s], Bh[0], Bh[1]);
                MMA_BF16(S[nt], qfh[s], Bl[0], Bl[1]);
                MMA_BF16(S[nt], qfh[s], Bh[0], Bh[1]);
            }
        }

        if (kt < q0 - 64 || kt > q0 + 64) {
            #pragma unroll
            for (int nt = 0; nt < 8; nt++)
                #pragma unroll
                for (int c = 0; c < 4; c++) {
                    int j = kt + nt * 8 + 2 * t + (c & 1);
                    int i = i0 + ((c >> 1) << 3);
                    if (j < i - WL || j > i + WR) S[nt][c] = -1e30f;
                }
        }

        float mx0 = -1e30f, mx1 = -1e30f;
        #pragma unroll
        for (int nt = 0; nt < 8; nt++) {
            mx0 = fmaxf(mx0, fmaxf(S[nt][0], S[nt][1]));
            mx1 = fmaxf(mx1, fmaxf(S[nt][2], S[nt][3]));
        }
        mx0 = fmaxf(mx0, __shfl_xor_sync(0xffffffffu, mx0, 1));
        mx0 = fmaxf(mx0, __shfl_xor_sync(0xffffffffu, mx0, 2));
        mx1 = fmaxf(mx1, __shfl_xor_sync(0xffffffffu, mx1, 1));
        mx1 = fmaxf(mx1, __shfl_xor_sync(0xffffffffu, mx1, 2));

        float mn0 = fmaxf(m0, mx0), mn1 = fmaxf(m1, mx1);
        float cr0 = __expf(m0 - mn0), cr1 = __expf(m1 - mn1);
        float mc0 = fmaxf(mn0, -1e29f), mc1 = fmaxf(mn1, -1e29f);

        float sum0 = 0.0f, sum1 = 0.0f;
        #pragma unroll
        for (int nt = 0; nt < 8; nt++) {
            S[nt][0] = __expf(S[nt][0] - mc0);
            S[nt][1] = __expf(S[nt][1] - mc0);
            S[nt][2] = __expf(S[nt][2] - mc1);
            S[nt][3] = __expf(S[nt][3] - mc1);
            sum0 += S[nt][0] + S[nt][1];
            sum1 += S[nt][2] + S[nt][3];
        }
        sum0 += __shfl_xor_sync(0xffffffffu, sum0, 1);
        sum0 += __shfl_xor_sync(0xffffffffu, sum0, 2);
        sum1 += __shfl_xor_sync(0xffffffffu, sum1, 1);
        sum1 += __shfl_xor_sync(0xffffffffu, sum1, 2);
        l0 = l0 * cr0 + sum0;
        l1 = l1 * cr1 + sum1;
        m0 = mn0; m1 = mn1;

        #pragma unroll
        for (int nd = 0; nd < 8; nd++) {
            O[nd][0] *= cr0; O[nd][1] *= cr0;
            O[nd][2] *= cr1; O[nd][3] *= cr1;
        }

        #pragma unroll
        for (int s2 = 0; s2 < 4; s2++) {
            uint32_t pah[4], pal[4];
            pah[0] = pack_hi_lo(S[2 * s2][0],     S[2 * s2][1],     pal[0]);
            pah[1] = pack_hi_lo(S[2 * s2][2],     S[2 * s2][3],     pal[1]);
            pah[2] = pack_hi_lo(S[2 * s2 + 1][0], S[2 * s2 + 1][1], pal[2]);
            pah[3] = pack_hi_lo(S[2 * s2 + 1][2], S[2 * s2 + 1][3], pal[3]);

            uint32_t vbh[4][4], vbl[4][4];
            #pragma unroll
            for (int j = 0; j < 4; j++) {
                uint32_t off = (uint32_t)((j * 16 + bRow) * SRB + bKb + s2 * 32);
                ldsm_x4(vbh[j], sVh + off);
                ldsm_x4(vbl[j], sVl + off);
            }
            #pragma unroll
            for (int nd = 0; nd < 8; nd++) {
                const uint32_t* Bh = &vbh[nd >> 1][(nd & 1) * 2];
                const uint32_t* Bl = &vbl[nd >> 1][(nd & 1) * 2];
                MMA_BF16(O[nd], pal, Bh[0], Bh[1]);
                MMA_BF16(O[nd], pah, Bl[0], Bl[1]);
                MMA_BF16(O[nd], pah, Bh[0], Bh[1]);
            }
        }
        __syncthreads();
    }

    const float inv0 = 1.0f / l0, inv1 = 1.0f / l1;
    const int r0 = i0, r1 = i0 + 8;
    #pragma unroll
    for (int nd = 0; nd < 8; nd++) {
        const int col = h * HDD + nd * 8 + 2 * t;
        uint32_t lo0, lo1;
        uint32_t hi0 = pack_hi_lo(O[nd][0] * inv0, O[nd][1] * inv0, lo0);
        uint32_t hi1 = pack_hi_lo(O[nd][2] * inv1, O[nd][3] * inv1, lo1);
        *(uint32_t*)(Oh + (size_t)(n * TT + r0) * DD + col) = hi0;
        *(uint32_t*)(Ol + (size_t)(n * TT + r0) * DD + col) = lo0;
        *(uint32_t*)(Oh + (size_t)(n * TT + r1) * DD + col) = hi1;
        *(uint32_t*)(Ol + (size_t)(n * TT + r1) * DD + col) = lo1;
    }
}

// ---------------------------------------------------------------------------
extern "C" void kernel_launch(void* const* d_in, const int* in_sizes, int n_in,
                              void* d_out, int out_size)
{
    const float* x     = (const float*)d_in[0];
    const float* w_qkv = (const float*)d_in[1];
    const float* w_out = (const float*)d_in[2];
    const float* b_out = (const float*)d_in[3];
    float* out = (float*)d_out;

    uint16_t *ahi, *alo, *bhi, *blo, *qh, *ql, *kh, *kl, *vth, *vtl;
    cudaGetSymbolAddress((void**)&ahi, g_ahi);
    cudaGetSymbolAddress((void**)&alo, g_alo);
    cudaGetSymbolAddress((void**)&bhi, g_bhi);
    cudaGetSymbolAddress((void**)&blo, g_blo);
    cudaGetSymbolAddress((void**)&qh,  g_qh);
    cudaGetSymbolAddress((void**)&ql,  g_ql);
    cudaGetSymbolAddress((void**)&kh,  g_kh);
    cudaGetSymbolAddress((void**)&kl,  g_kl);
    cudaGetSymbolAddress((void**)&vth, g_vth);
    cudaGetSymbolAddress((void**)&vtl, g_vtl);

    const int M = NB * TT;                 // 4096

    cudaFuncSetAttribute(gemm_3xbf16, cudaFuncAttributeMaxDynamicSharedMemorySize,
                         GSMEM);

    // split x and w_qkv
    {
        int n4 = M * DD / 4;
        split_kernel<<<(n4 + 255) / 256, 256>>>(x, ahi, alo, n4);
        n4 = 3 * DD * DD / 4;
        split_kernel<<<(n4 + 255) / 256, 256>>>(w_qkv, bhi, blo, n4);
    }
    // 1) fused: qkv GEMM + RoPE + split + v-transpose -> attention planes
    {
        dim3 grid(3 * DD / 128, M / 128);
        gemm_3xbf16<<<grid, 256, GSMEM>>>(ahi, alo, bhi, blo, nullptr, nullptr,
                                          M, 3 * DD, DD, 1);
    }
    // 2) flash attention -> writes A planes for GEMM2
    {
        dim3 grid(TT / 64, HH, NB);
        attn_mma<<<grid, 128>>>(qh, ql, kh, kl, vth, vtl, ahi, alo);
    }
    // split w_out
    {
        int n4 = DD * DD / 4;
        split_kernel<<<(n4 + 255) / 256, 256>>>(w_out, bhi, blo, n4);
    }
    // 3) out = attn @ w_out^T + b_out
    {
        dim3 grid(DD / 128, M / 128);
        gemm_3xbf16<<<grid, 256, GSMEM>>>(ahi, alo, bhi, blo, b_out, out,
                                          M, DD, DD, 0);
    }
}